// round 12
// baseline (speedup 1.0000x reference)
#include <cuda_runtime.h>
#include <cstdint>

// out = x + exp(0.5*(relu(x@W1+b1)@W2 + b2)) * eps
// Persistent mma.sync tf32 kernel, 512 threads.
// R10 base + GEMM2 4x4 warp tiling (2x W2 B-fragment reuse).

#define SDIM 256
#define TMR  128
#define NTHREADS 512

// smem float-index offsets
#define W1F 0          // W1 tf32 [k=256][64] XOR-swizzled   (64 KB)
#define W2F 16384      // W2 tf32 [k=64][256] XOR-swizzled   (64 KB)
#define XSF 32768      // X ring: 2 slots x (128 rows x 32k) (32 KB)
#define HSF 40960      // H tf32: 128 x 64, swizzled         (32 KB)
#define EPF 49152      // eps: 16 warps x 2 bufs x 256 fl    (32 KB)
#define B1S 57344      // 64 f32
#define B2S 57408      // 256 f32
#define SMEM_FLOATS 57664
#define SMEM_BYTES  (SMEM_FLOATS * 4)   // 230656

__device__ __forceinline__ uint32_t to_tf32(float f) {
    uint32_t r; asm("cvt.rna.tf32.f32 %0, %1;" : "=r"(r) : "f"(f)); return r;
}
__device__ __forceinline__ float ex2f(float f) {
    float r; asm("ex2.approx.f32 %0, %1;" : "=f"(r) : "f"(f)); return r;
}
__device__ __forceinline__ void mma8(float* c,
    uint32_t a0, uint32_t a1, uint32_t a2, uint32_t a3, uint32_t b0, uint32_t b1) {
    asm volatile(
        "mma.sync.aligned.m16n8k8.row.col.f32.tf32.tf32.f32 "
        "{%0,%1,%2,%3},{%4,%5,%6,%7},{%8,%9},{%0,%1,%2,%3};"
        : "+f"(c[0]), "+f"(c[1]), "+f"(c[2]), "+f"(c[3])
        : "r"(a0), "r"(a1), "r"(a2), "r"(a3), "r"(b0), "r"(b1));
}
static __device__ __forceinline__ uint32_t smem_u32(const void* p) {
    uint32_t a;
    asm("{ .reg .u64 t; cvta.to.shared.u64 t, %1; cvt.u32.u64 %0, t; }" : "=r"(a) : "l"(p));
    return a;
}
#define CPA16(s, g)  asm volatile("cp.async.cg.shared.global [%0], [%1], 16;" :: "r"(s), "l"(g))
#define CPCOMMIT()   asm volatile("cp.async.commit_group;" ::: "memory")
#define CPWAIT1()    asm volatile("cp.async.wait_group 1;" ::: "memory")

// block-cooperative load of one X chunk (128 rows x 32 floats) into a slot
static __device__ __forceinline__ void load_chunkX(
    const float* __restrict__ gsrc, float* slot) {
    const int tid = threadIdx.x;
    #pragma unroll
    for (int p = 0; p < 2; p++) {
        int f = tid + NTHREADS * p;         // float4 index, 1024 total
        int m = f >> 3, c4 = f & 7;
        uint32_t dst = smem_u32(slot + m * 32 + 4 * (c4 ^ (m & 7)));
        CPA16(dst, gsrc + m * SDIM + 4 * c4);
    }
}

// per-warp load of one eps chunk e (16 rows x 16 cols) into its private buffer
// chunk e: rows 32*wq + 16*(e&1) .., cols 64*nq + 16*(e>>1) ..
static __device__ __forceinline__ void load_eps(
    const float* __restrict__ eT, int e, int wq, int nq, int lane, float* ebuf) {
    #pragma unroll
    for (int p = 0; p < 2; p++) {
        int f = lane + 32 * p;              // 0..63 float4s
        int rr = f >> 2, u = f & 3;
        uint32_t dst = smem_u32(ebuf + rr * 16 + 4 * (u ^ (rr & 3)));
        CPA16(dst, eT + (32 * wq + 16 * (e & 1) + rr) * SDIM
                     + 64 * nq + 16 * (e >> 1) + 4 * u);
    }
}

__global__ void __launch_bounds__(NTHREADS, 1) mvn_sq_kernel(
    const float* __restrict__ x, const float* __restrict__ eps,
    const float* __restrict__ W1, const float* __restrict__ b1,
    const float* __restrict__ W2, const float* __restrict__ b2,
    float* __restrict__ out, int numTiles)
{
    extern __shared__ float sm[];
    uint32_t* smu = reinterpret_cast<uint32_t*>(sm);

    const int tid  = threadIdx.x;
    const int w    = tid >> 5;
    const int wh   = w & 7;       // GEMM1 row group (16 rows)
    const int ns   = w >> 3;      // GEMM1 column half
    const int wq   = w & 3;       // GEMM2 row quad (32 rows)
    const int nq   = w >> 2;      // GEMM2 column quarter (64 cols)
    const int lane = tid & 31;
    const int g    = lane >> 2;
    const int t4   = lane & 3;

    // ---- stage weights (tf32, XOR-swizzled) + biases ----
    #pragma unroll 4
    for (int j = 0; j < 32; j++) {
        int idx = tid + NTHREADS * j;
        int kk = idx >> 6, n = idx & 63;
        smu[W1F + kk * 64 + (n ^ (8 * (kk & 3)))] = to_tf32(W1[idx]);
    }
    #pragma unroll 4
    for (int j = 0; j < 32; j++) {
        int idx = tid + NTHREADS * j;
        int kk = idx >> 8, n = idx & 255;
        smu[W2F + kk * 256 + (n ^ (8 * (kk & 3)))] = to_tf32(W2[idx]);
    }
    if (tid < 64) sm[B1S + tid] = b1[tid];
    if (tid >= 64 && tid < 320) sm[B2S + tid - 64] = b2[tid - 64];
    __syncthreads();

    const int G = gridDim.x;
    const long long TS = (long long)TMR * SDIM;
    int t = blockIdx.x;

    float* slot0 = sm + XSF;
    float* slot1 = sm + XSF + 4096;
    float* ebuf0 = sm + EPF + w * 512;
    float* ebuf1 = ebuf0 + 256;
    const uint32_t* Hs = smu + HSF;

    load_chunkX(x + t * TS + 0 * 32, slot0); CPCOMMIT();   // {X0}
    load_chunkX(x + t * TS + 1 * 32, slot1); CPCOMMIT();   // {X1}

    const int arowX = (16 * wh + g) * 32 + t4;   // X A-fragment base (K=32 slots)

    for (; t < numTiles; t += G) {
        const long long base = t * TS;
        const float* xT = x + base;
        const float* eT = eps + base;
        float* oT = out + base;

        // ======== GEMM1: this warp -> H cols 32*ns..+31 (8 K=32 chunks) ========
        float acc1[4][4];
        #pragma unroll
        for (int nt = 0; nt < 4; nt++)
            acc1[nt][0] = acc1[nt][1] = acc1[nt][2] = acc1[nt][3] = 0.0f;

        #pragma unroll
        for (int c = 0; c < 8; c++) {
            CPWAIT1();
            __syncthreads();
            const float* xs = (c & 1) ? slot1 : slot0;

            #pragma unroll
            for (int ks = 0; ks < 4; ks++) {
                int a0i = arowX + 4 * ((2 * ks) ^ g);
                uint32_t A0 = to_tf32(xs[a0i]);
                uint32_t A1 = to_tf32(xs[a0i + 256]);
                uint32_t A2 = to_tf32(xs[a0i ^ 4]);
                uint32_t A3 = to_tf32(xs[(a0i ^ 4) + 256]);
                const uint32_t* bp = smu + W1F + (32 * c + 8 * ks + t4) * 64 + 32 * ns + g;
                #pragma unroll
                for (int nt = 0; nt < 4; nt++) {
                    int o = 8 * (nt ^ t4);
                    mma8(acc1[nt], A0, A1, A2, A3, bp[o], bp[o + 256]);
                }
            }
            __syncthreads();

            float* slot = (c & 1) ? slot1 : slot0;
            if (c < 6) {
                load_chunkX(xT + (c + 2) * 32, slot);
            } else {
                int tn = t + G;
                if (tn < numTiles) load_chunkX(x + tn * TS + (c - 6) * 32, slot);
                // bundle eps chunks 0/1 for THIS tile's epilogue
                load_eps(eT, c - 6, wq, nq, lane, (c == 6) ? ebuf0 : ebuf1);
            }
            CPCOMMIT();
        }

        // ---- bias + relu -> H (tf32, swizzled) ----
        {
            const int m0 = (16 * wh + g) * 64;
            #pragma unroll
            for (int nt = 0; nt < 4; nt++) {
                int col = 32 * ns + 8 * nt + 2 * t4;
                float2 bb = *reinterpret_cast<const float2*>(&sm[B1S + col]);
                uint2 p0, p1;
                p0.x = to_tf32(fmaxf(acc1[nt][0] + bb.x, 0.0f));
                p0.y = to_tf32(fmaxf(acc1[nt][1] + bb.y, 0.0f));
                p1.x = to_tf32(fmaxf(acc1[nt][2] + bb.x, 0.0f));
                p1.y = to_tf32(fmaxf(acc1[nt][3] + bb.y, 0.0f));
                int hi = m0 + 4 * ((col >> 2) ^ g) + (col & 3);
                *reinterpret_cast<uint2*>(&smu[HSF + hi])       = p0;
                *reinterpret_cast<uint2*>(&smu[HSF + hi + 512]) = p1;
            }
        }
        __syncthreads();

        // ---- preload H A-fragments for BOTH m-frags (rows 32wq..+31): 64 regs ----
        uint4 hA[16];
        #pragma unroll
        for (int mf = 0; mf < 2; mf++) {
            const int arowH = (32 * wq + 16 * mf + g) * 64 + t4;
            #pragma unroll
            for (int ks = 0; ks < 8; ks++) {
                int a0i = arowH + 4 * ((2 * ks) ^ g);
                hA[8 * mf + ks].x = Hs[a0i];
                hA[8 * mf + ks].y = Hs[a0i + 512];
                hA[8 * mf + ks].z = Hs[a0i ^ 4];
                hA[8 * mf + ks].w = Hs[(a0i ^ 4) + 512];
            }
        }

        // ======== GEMM2 + epilogue: 4 j-chunks of 16 cols, rows 32wq..+31 ========
        #pragma unroll
        for (int j = 0; j < 4; j++) {
            const int colb = 64 * nq + 16 * j + 2 * t4;

            // x loads for half 0 (hidden under MMAs)
            float2 xv0[2][2];
            #pragma unroll
            for (int nt = 0; nt < 2; nt++)
                #pragma unroll
                for (int hi = 0; hi < 2; hi++)
                    xv0[nt][hi] = *reinterpret_cast<const float2*>(
                        &xT[(32 * wq + 8 * hi + g) * SDIM + colb + 8 * nt]);

            float acc2[2][2][4];
            #pragma unroll
            for (int mf = 0; mf < 2; mf++)
                #pragma unroll
                for (int nt = 0; nt < 2; nt++)
                    acc2[mf][nt][0] = acc2[mf][nt][1] =
                    acc2[mf][nt][2] = acc2[mf][nt][3] = 0.0f;

            const int nc0 = 64 * nq + 16 * j + g;
            const int i0 = nc0 ^ (8 * t4);
            const int i1 = (nc0 + 8) ^ (8 * t4);
            #pragma unroll
            for (int ks = 0; ks < 8; ks++) {
                const uint32_t* bp = smu + W2F + (8 * ks + t4) * 256;
                uint32_t b00 = bp[i0], b01 = bp[i1];
                uint32_t b10 = bp[1024 + i0], b11 = bp[1024 + i1];
                mma8(acc2[0][0], hA[ks].x, hA[ks].y, hA[ks].z, hA[ks].w, b00, b10);
                mma8(acc2[0][1], hA[ks].x, hA[ks].y, hA[ks].z, hA[ks].w, b01, b11);
                mma8(acc2[1][0], hA[8+ks].x, hA[8+ks].y, hA[8+ks].z, hA[8+ks].w, b00, b10);
                mma8(acc2[1][1], hA[8+ks].x, hA[8+ks].y, hA[8+ks].z, hA[8+ks].w, b01, b11);
            }

            float2 bb[2];
            bb[0] = *reinterpret_cast<const float2*>(&sm[B2S + colb]);
            bb[1] = *reinterpret_cast<const float2*>(&sm[B2S + colb + 8]);

            // ---- half 0 (rows 32wq..+15, eps chunk 2j in ebuf0) ----
            CPWAIT1();
            __syncwarp();
            #pragma unroll
            for (int nt = 0; nt < 2; nt++) {
                #pragma unroll
                for (int hi = 0; hi < 2; hi++) {
                    int rr = g + 8 * hi;
                    int u  = (2 * nt + (t4 >> 1)) ^ (rr & 3);
                    float2 ev = *reinterpret_cast<const float2*>(
                        &ebuf0[rr * 16 + 4 * u + 2 * (t4 & 1)]);
                    int row = 32 * wq + 8 * hi + g;
                    float s0 = ex2f((acc2[0][nt][2 * hi]     + bb[nt].x) * 0.72134752044f);
                    float s1 = ex2f((acc2[0][nt][2 * hi + 1] + bb[nt].y) * 0.72134752044f);
                    float2 o;
                    o.x = fmaf(s0, ev.x, xv0[nt][hi].x);
                    o.y = fmaf(s1, ev.y, xv0[nt][hi].y);
                    *reinterpret_cast<float2*>(&oT[row * SDIM + colb + 8 * nt]) = o;
                }
            }
            __syncwarp();
            if (2 * j + 2 < 8) load_eps(eT, 2 * j + 2, wq, nq, lane, ebuf0);
            CPCOMMIT();

            // x loads for half 1
            float2 xv1[2][2];
            #pragma unroll
            for (int nt = 0; nt < 2; nt++)
                #pragma unroll
                for (int hi = 0; hi < 2; hi++)
                    xv1[nt][hi] = *reinterpret_cast<const float2*>(
                        &xT[(32 * wq + 16 + 8 * hi + g) * SDIM + colb + 8 * nt]);

            // ---- half 1 (rows 32wq+16..+31, eps chunk 2j+1 in ebuf1) ----
            CPWAIT1();
            __syncwarp();
            #pragma unroll
            for (int nt = 0; nt < 2; nt++) {
                #pragma unroll
                for (int hi = 0; hi < 2; hi++) {
                    int rr = g + 8 * hi;
                    int u  = (2 * nt + (t4 >> 1)) ^ (rr & 3);
                    float2 ev = *reinterpret_cast<const float2*>(
                        &ebuf1[rr * 16 + 4 * u + 2 * (t4 & 1)]);
                    int row = 32 * wq + 16 + 8 * hi + g;
                    float s0 = ex2f((acc2[1][nt][2 * hi]     + bb[nt].x) * 0.72134752044f);
                    float s1 = ex2f((acc2[1][nt][2 * hi + 1] + bb[nt].y) * 0.72134752044f);
                    float2 o;
                    o.x = fmaf(s0, ev.x, xv1[nt][hi].x);
                    o.y = fmaf(s1, ev.y, xv1[nt][hi].y);
                    *reinterpret_cast<float2*>(&oT[row * SDIM + colb + 8 * nt]) = o;
                }
            }
            __syncwarp();
            if (2 * j + 3 < 8) load_eps(eT, 2 * j + 3, wq, nq, lane, ebuf1);
            CPCOMMIT();
        }
        // next tile's GEMM1 barriers provide X-slot ordering
    }
}

extern "C" void kernel_launch(void* const* d_in, const int* in_sizes, int n_in,
                              void* d_out, int out_size) {
    const float* x   = (const float*)d_in[0];
    const float* eps = (const float*)d_in[1];
    const float* W1  = (const float*)d_in[2];
    const float* b1  = (const float*)d_in[3];
    const float* W2  = (const float*)d_in[4];
    const float* b2  = (const float*)d_in[5];
    float* out = (float*)d_out;

    int B = in_sizes[0] / SDIM;
    int numTiles = B / TMR;   // 1024

    static int sms = 0;
    if (!sms) {
        cudaDeviceGetAttribute(&sms, cudaDevAttrMultiProcessorCount, 0);
        cudaFuncSetAttribute(mvn_sq_kernel,
                             cudaFuncAttributeMaxDynamicSharedMemorySize, SMEM_BYTES);
    }
    int grid = sms < numTiles ? sms : numTiles;

    mvn_sq_kernel<<<grid, NTHREADS, SMEM_BYTES>>>(x, eps, W1, b1, W2, b2, out, numTiles);
}

// round 15
// speedup vs baseline: 1.0233x; 1.0233x over previous
#include <cuda_runtime.h>
#include <cstdint>

// out = x + exp(0.5*(relu(x@W1+b1)@W2 + b2)) * eps
// Persistent mma.sync tf32 kernel, 512 threads.
// R12 base + pair-private X loading/sync: GEMM1 uses named pair barriers,
// only 2 block-wide barriers per tile.

#define SDIM 256
#define TMR  128
#define NTHREADS 512

// smem float-index offsets
#define W1F 0          // W1 tf32 [k=256][64] XOR-swizzled   (64 KB)
#define W2F 16384      // W2 tf32 [k=64][256] XOR-swizzled   (64 KB)
#define XSF 32768      // X ring: 2 slots x (128 rows x 32k) (32 KB)
#define HSF 40960      // H tf32: 128 x 64, swizzled         (32 KB)
#define EPF 49152      // eps: 16 warps x 2 bufs x 256 fl    (32 KB)
#define B1S 57344      // 64 f32
#define B2S 57408      // 256 f32
#define SMEM_FLOATS 57664
#define SMEM_BYTES  (SMEM_FLOATS * 4)   // 230656

__device__ __forceinline__ uint32_t to_tf32(float f) {
    uint32_t r; asm("cvt.rna.tf32.f32 %0, %1;" : "=r"(r) : "f"(f)); return r;
}
__device__ __forceinline__ float ex2f(float f) {
    float r; asm("ex2.approx.f32 %0, %1;" : "=f"(r) : "f"(f)); return r;
}
__device__ __forceinline__ void mma8(float* c,
    uint32_t a0, uint32_t a1, uint32_t a2, uint32_t a3, uint32_t b0, uint32_t b1) {
    asm volatile(
        "mma.sync.aligned.m16n8k8.row.col.f32.tf32.tf32.f32 "
        "{%0,%1,%2,%3},{%4,%5,%6,%7},{%8,%9},{%0,%1,%2,%3};"
        : "+f"(c[0]), "+f"(c[1]), "+f"(c[2]), "+f"(c[3])
        : "r"(a0), "r"(a1), "r"(a2), "r"(a3), "r"(b0), "r"(b1));
}
static __device__ __forceinline__ uint32_t smem_u32(const void* p) {
    uint32_t a;
    asm("{ .reg .u64 t; cvta.to.shared.u64 t, %1; cvt.u32.u64 %0, t; }" : "=r"(a) : "l"(p));
    return a;
}
#define CPA16(s, g)  asm volatile("cp.async.cg.shared.global [%0], [%1], 16;" :: "r"(s), "l"(g))
#define CPCOMMIT()   asm volatile("cp.async.commit_group;" ::: "memory")
#define CPWAIT1()    asm volatile("cp.async.wait_group 1;" ::: "memory")
#define PAIRBAR(id)  asm volatile("bar.sync %0, 64;" :: "r"(id) : "memory")

// pair-split load of one X chunk: warp loads rows 16*wh..+15, cols 16*ns..+15.
// Pair {w, w+8} (same wh, ns=0/1) jointly covers rows 16*wh x 32 cols.
static __device__ __forceinline__ void load_chunkX_p(
    const float* __restrict__ gsrc, float* slot, int wh, int ns, int lane) {
    #pragma unroll
    for (int p = 0; p < 2; p++) {
        int f = lane + 32 * p;          // 0..63 float4s
        int mr = f >> 2, u = f & 3;
        int m = 16 * wh + mr;
        int c4 = 4 * ns + u;
        uint32_t dst = smem_u32(slot + m * 32 + 4 * (c4 ^ (m & 7)));
        CPA16(dst, gsrc + m * SDIM + 4 * c4);
    }
}

// per-warp load of one eps chunk e (16 rows x 16 cols) into its private buffer
// chunk e: rows 32*wq + 16*(e&1) .., cols 64*nq + 16*(e>>1) ..
static __device__ __forceinline__ void load_eps(
    const float* __restrict__ eT, int e, int wq, int nq, int lane, float* ebuf) {
    #pragma unroll
    for (int p = 0; p < 2; p++) {
        int f = lane + 32 * p;          // 0..63 float4s
        int rr = f >> 2, u = f & 3;
        uint32_t dst = smem_u32(ebuf + rr * 16 + 4 * (u ^ (rr & 3)));
        CPA16(dst, eT + (32 * wq + 16 * (e & 1) + rr) * SDIM
                     + 64 * nq + 16 * (e >> 1) + 4 * u);
    }
}

__global__ void __launch_bounds__(NTHREADS, 1) mvn_pb_kernel(
    const float* __restrict__ x, const float* __restrict__ eps,
    const float* __restrict__ W1, const float* __restrict__ b1,
    const float* __restrict__ W2, const float* __restrict__ b2,
    float* __restrict__ out, int numTiles)
{
    extern __shared__ float sm[];
    uint32_t* smu = reinterpret_cast<uint32_t*>(sm);

    const int tid  = threadIdx.x;
    const int w    = tid >> 5;
    const int wh   = w & 7;       // GEMM1 row group (16 rows); pair id
    const int ns   = w >> 3;      // GEMM1 column half
    const int wq   = w & 3;       // GEMM2 row quad (32 rows)
    const int nq   = w >> 2;      // GEMM2 column quarter (64 cols)
    const int lane = tid & 31;
    const int g    = lane >> 2;
    const int t4   = lane & 3;
    const int pbar = 1 + wh;      // named barrier id for this pair (1..8)

    // ---- stage weights (tf32, XOR-swizzled) + biases ----
    #pragma unroll 4
    for (int j = 0; j < 32; j++) {
        int idx = tid + NTHREADS * j;
        int kk = idx >> 6, n = idx & 63;
        smu[W1F + kk * 64 + (n ^ (8 * (kk & 3)))] = to_tf32(W1[idx]);
    }
    #pragma unroll 4
    for (int j = 0; j < 32; j++) {
        int idx = tid + NTHREADS * j;
        int kk = idx >> 8, n = idx & 255;
        smu[W2F + kk * 256 + (n ^ (8 * (kk & 3)))] = to_tf32(W2[idx]);
    }
    if (tid < 64) sm[B1S + tid] = b1[tid];
    if (tid >= 64 && tid < 320) sm[B2S + tid - 64] = b2[tid - 64];
    __syncthreads();

    const int G = gridDim.x;
    const long long TS = (long long)TMR * SDIM;
    int t = blockIdx.x;

    float* slot0 = sm + XSF;
    float* slot1 = sm + XSF + 4096;
    float* ebuf0 = sm + EPF + w * 512;
    float* ebuf1 = ebuf0 + 256;
    const uint32_t* Hs = smu + HSF;

    // pair-split prefetch of first tile's chunks 0,1
    load_chunkX_p(x + t * TS + 0 * 32, slot0, wh, ns, lane); CPCOMMIT();
    load_chunkX_p(x + t * TS + 1 * 32, slot1, wh, ns, lane); CPCOMMIT();

    const int arowX = (16 * wh + g) * 32 + t4;   // X A-fragment base

    for (; t < numTiles; t += G) {
        const long long base = t * TS;
        const float* xT = x + base;
        const float* eT = eps + base;
        float* oT = out + base;

        // ======== GEMM1: pair-synchronized, no block barriers ========
        float acc1[4][4];
        #pragma unroll
        for (int nt = 0; nt < 4; nt++)
            acc1[nt][0] = acc1[nt][1] = acc1[nt][2] = acc1[nt][3] = 0.0f;

        #pragma unroll
        for (int c = 0; c < 8; c++) {
            CPWAIT1();          // own cp.asyncs for chunk c done
            PAIRBAR(pbar);      // partner's too; cross-warp visibility
            const float* xs = (c & 1) ? slot1 : slot0;

            #pragma unroll
            for (int ks = 0; ks < 4; ks++) {
                int a0i = arowX + 4 * ((2 * ks) ^ g);
                uint32_t A0 = to_tf32(xs[a0i]);
                uint32_t A1 = to_tf32(xs[a0i + 256]);
                uint32_t A2 = to_tf32(xs[a0i ^ 4]);
                uint32_t A3 = to_tf32(xs[(a0i ^ 4) + 256]);
                const uint32_t* bp = smu + W1F + (32 * c + 8 * ks + t4) * 64 + 32 * ns + g;
                #pragma unroll
                for (int nt = 0; nt < 4; nt++) {
                    int o = 8 * (nt ^ t4);
                    mma8(acc1[nt], A0, A1, A2, A3, bp[o], bp[o + 256]);
                }
            }
            PAIRBAR(pbar);      // both warps done reading this slot's rows

            float* slot = (c & 1) ? slot1 : slot0;
            if (c < 6) {
                load_chunkX_p(xT + (c + 2) * 32, slot, wh, ns, lane);
            } else {
                int tn = t + G;
                if (tn < numTiles)
                    load_chunkX_p(x + tn * TS + (c - 6) * 32, slot, wh, ns, lane);
                // bundle eps chunks 0/1 for THIS tile's epilogue
                load_eps(eT, c - 6, wq, nq, lane, (c == 6) ? ebuf0 : ebuf1);
            }
            CPCOMMIT();
        }

        // ---- bias + relu -> H (tf32, swizzled) ----
        {
            const int m0 = (16 * wh + g) * 64;
            #pragma unroll
            for (int nt = 0; nt < 4; nt++) {
                int col = 32 * ns + 8 * nt + 2 * t4;
                float2 bb = *reinterpret_cast<const float2*>(&sm[B1S + col]);
                uint2 p0, p1;
                p0.x = to_tf32(fmaxf(acc1[nt][0] + bb.x, 0.0f));
                p0.y = to_tf32(fmaxf(acc1[nt][1] + bb.y, 0.0f));
                p1.x = to_tf32(fmaxf(acc1[nt][2] + bb.x, 0.0f));
                p1.y = to_tf32(fmaxf(acc1[nt][3] + bb.y, 0.0f));
                int hi = m0 + 4 * ((col >> 2) ^ g) + (col & 3);
                *reinterpret_cast<uint2*>(&smu[HSF + hi])       = p0;
                *reinterpret_cast<uint2*>(&smu[HSF + hi + 512]) = p1;
            }
        }
        __syncthreads();   // block barrier 1: H ready

        // ---- preload H A-fragments for BOTH m-frags (rows 32wq..+31) ----
        uint4 hA[16];
        #pragma unroll
        for (int mf = 0; mf < 2; mf++) {
            const int arowH = (32 * wq + 16 * mf + g) * 64 + t4;
            #pragma unroll
            for (int ks = 0; ks < 8; ks++) {
                int a0i = arowH + 4 * ((2 * ks) ^ g);
                hA[8 * mf + ks].x = Hs[a0i];
                hA[8 * mf + ks].y = Hs[a0i + 512];
                hA[8 * mf + ks].z = Hs[a0i ^ 4];
                hA[8 * mf + ks].w = Hs[(a0i ^ 4) + 512];
            }
        }

        // ======== GEMM2 + epilogue: 4 j-chunks of 16 cols, rows 32wq..+31 ========
        #pragma unroll
        for (int j = 0; j < 4; j++) {
            const int colb = 64 * nq + 16 * j + 2 * t4;

            // x loads for half 0 (hidden under MMAs)
            float2 xv0[2][2];
            #pragma unroll
            for (int nt = 0; nt < 2; nt++)
                #pragma unroll
                for (int hi = 0; hi < 2; hi++)
                    xv0[nt][hi] = *reinterpret_cast<const float2*>(
                        &xT[(32 * wq + 8 * hi + g) * SDIM + colb + 8 * nt]);

            float acc2[2][2][4];
            #pragma unroll
            for (int mf = 0; mf < 2; mf++)
                #pragma unroll
                for (int nt = 0; nt < 2; nt++)
                    acc2[mf][nt][0] = acc2[mf][nt][1] =
                    acc2[mf][nt][2] = acc2[mf][nt][3] = 0.0f;

            const int nc0 = 64 * nq + 16 * j + g;
            const int i0 = nc0 ^ (8 * t4);
            const int i1 = (nc0 + 8) ^ (8 * t4);
            #pragma unroll
            for (int ks = 0; ks < 8; ks++) {
                const uint32_t* bp = smu + W2F + (8 * ks + t4) * 256;
                uint32_t b00 = bp[i0], b01 = bp[i1];
                uint32_t b10 = bp[1024 + i0], b11 = bp[1024 + i1];
                mma8(acc2[0][0], hA[ks].x, hA[ks].y, hA[ks].z, hA[ks].w, b00, b10);
                mma8(acc2[0][1], hA[ks].x, hA[ks].y, hA[ks].z, hA[ks].w, b01, b11);
                mma8(acc2[1][0], hA[8+ks].x, hA[8+ks].y, hA[8+ks].z, hA[8+ks].w, b00, b10);
                mma8(acc2[1][1], hA[8+ks].x, hA[8+ks].y, hA[8+ks].z, hA[8+ks].w, b01, b11);
            }

            float2 bb[2];
            bb[0] = *reinterpret_cast<const float2*>(&sm[B2S + colb]);
            bb[1] = *reinterpret_cast<const float2*>(&sm[B2S + colb + 8]);

            // ---- half 0 (rows 32wq..+15, eps chunk 2j in ebuf0) ----
            CPWAIT1();
            __syncwarp();
            #pragma unroll
            for (int nt = 0; nt < 2; nt++) {
                #pragma unroll
                for (int hi = 0; hi < 2; hi++) {
                    int rr = g + 8 * hi;
                    int u  = (2 * nt + (t4 >> 1)) ^ (rr & 3);
                    float2 ev = *reinterpret_cast<const float2*>(
                        &ebuf0[rr * 16 + 4 * u + 2 * (t4 & 1)]);
                    int row = 32 * wq + 8 * hi + g;
                    float s0 = ex2f((acc2[0][nt][2 * hi]     + bb[nt].x) * 0.72134752044f);
                    float s1 = ex2f((acc2[0][nt][2 * hi + 1] + bb[nt].y) * 0.72134752044f);
                    float2 o;
                    o.x = fmaf(s0, ev.x, xv0[nt][hi].x);
                    o.y = fmaf(s1, ev.y, xv0[nt][hi].y);
                    *reinterpret_cast<float2*>(&oT[row * SDIM + colb + 8 * nt]) = o;
                }
            }
            __syncwarp();
            if (2 * j + 2 < 8) load_eps(eT, 2 * j + 2, wq, nq, lane, ebuf0);
            CPCOMMIT();

            // x loads for half 1
            float2 xv1[2][2];
            #pragma unroll
            for (int nt = 0; nt < 2; nt++)
                #pragma unroll
                for (int hi = 0; hi < 2; hi++)
                    xv1[nt][hi] = *reinterpret_cast<const float2*>(
                        &xT[(32 * wq + 16 + 8 * hi + g) * SDIM + colb + 8 * nt]);

            // ---- half 1 (rows 32wq+16..+31, eps chunk 2j+1 in ebuf1) ----
            CPWAIT1();
            __syncwarp();
            #pragma unroll
            for (int nt = 0; nt < 2; nt++) {
                #pragma unroll
                for (int hi = 0; hi < 2; hi++) {
                    int rr = g + 8 * hi;
                    int u  = (2 * nt + (t4 >> 1)) ^ (rr & 3);
                    float2 ev = *reinterpret_cast<const float2*>(
                        &ebuf1[rr * 16 + 4 * u + 2 * (t4 & 1)]);
                    int row = 32 * wq + 16 + 8 * hi + g;
                    float s0 = ex2f((acc2[1][nt][2 * hi]     + bb[nt].x) * 0.72134752044f);
                    float s1 = ex2f((acc2[1][nt][2 * hi + 1] + bb[nt].y) * 0.72134752044f);
                    float2 o;
                    o.x = fmaf(s0, ev.x, xv1[nt][hi].x);
                    o.y = fmaf(s1, ev.y, xv1[nt][hi].y);
                    *reinterpret_cast<float2*>(&oT[row * SDIM + colb + 8 * nt]) = o;
                }
            }
            __syncwarp();
            if (2 * j + 3 < 8) load_eps(eT, 2 * j + 3, wq, nq, lane, ebuf1);
            CPCOMMIT();
        }

        __syncthreads();   // block barrier 2: H consumed before next tile
    }
}

extern "C" void kernel_launch(void* const* d_in, const int* in_sizes, int n_in,
                              void* d_out, int out_size) {
    const float* x   = (const float*)d_in[0];
    const float* eps = (const float*)d_in[1];
    const float* W1  = (const float*)d_in[2];
    const float* b1  = (const float*)d_in[3];
    const float* W2  = (const float*)d_in[4];
    const float* b2  = (const float*)d_in[5];
    float* out = (float*)d_out;

    int B = in_sizes[0] / SDIM;
    int numTiles = B / TMR;   // 1024

    static int sms = 0;
    if (!sms) {
        cudaDeviceGetAttribute(&sms, cudaDevAttrMultiProcessorCount, 0);
        cudaFuncSetAttribute(mvn_pb_kernel,
                             cudaFuncAttributeMaxDynamicSharedMemorySize, SMEM_BYTES);
    }
    int grid = sms < numTiles ? sms : numTiles;

    mvn_pb_kernel<<<grid, NTHREADS, SMEM_BYTES>>>(x, eps, W1, b1, W2, b2, out, numTiles);
}

// round 16
// speedup vs baseline: 1.0502x; 1.0263x over previous
#include <cuda_runtime.h>
#include <cstdint>

// out = x + exp(0.5*(relu(x@W1+b1)@W2 + b2)) * eps
// Persistent mma.sync tf32 kernel, 512 threads.
// R15 base + early H retirement: the "H consumed" block barrier moves to
// right after the hA register preload, so the epilogue and next-tile GEMM1
// run barrier-free (cross-warp drift overlaps memory and tensor phases).

#define SDIM 256
#define TMR  128
#define NTHREADS 512

// smem float-index offsets
#define W1F 0          // W1 tf32 [k=256][64] XOR-swizzled   (64 KB)
#define W2F 16384      // W2 tf32 [k=64][256] XOR-swizzled   (64 KB)
#define XSF 32768      // X ring: 2 slots x (128 rows x 32k) (32 KB)
#define HSF 40960      // H tf32: 128 x 64, swizzled         (32 KB)
#define EPF 49152      // eps: 16 warps x 2 bufs x 256 fl    (32 KB)
#define B1S 57344      // 64 f32
#define B2S 57408      // 256 f32
#define SMEM_FLOATS 57664
#define SMEM_BYTES  (SMEM_FLOATS * 4)   // 230656

__device__ __forceinline__ uint32_t to_tf32(float f) {
    uint32_t r; asm("cvt.rna.tf32.f32 %0, %1;" : "=r"(r) : "f"(f)); return r;
}
__device__ __forceinline__ float ex2f(float f) {
    float r; asm("ex2.approx.f32 %0, %1;" : "=f"(r) : "f"(f)); return r;
}
__device__ __forceinline__ void mma8(float* c,
    uint32_t a0, uint32_t a1, uint32_t a2, uint32_t a3, uint32_t b0, uint32_t b1) {
    asm volatile(
        "mma.sync.aligned.m16n8k8.row.col.f32.tf32.tf32.f32 "
        "{%0,%1,%2,%3},{%4,%5,%6,%7},{%8,%9},{%0,%1,%2,%3};"
        : "+f"(c[0]), "+f"(c[1]), "+f"(c[2]), "+f"(c[3])
        : "r"(a0), "r"(a1), "r"(a2), "r"(a3), "r"(b0), "r"(b1));
}
static __device__ __forceinline__ uint32_t smem_u32(const void* p) {
    uint32_t a;
    asm("{ .reg .u64 t; cvta.to.shared.u64 t, %1; cvt.u32.u64 %0, t; }" : "=r"(a) : "l"(p));
    return a;
}
#define CPA16(s, g)  asm volatile("cp.async.cg.shared.global [%0], [%1], 16;" :: "r"(s), "l"(g))
#define CPCOMMIT()   asm volatile("cp.async.commit_group;" ::: "memory")
#define CPWAIT1()    asm volatile("cp.async.wait_group 1;" ::: "memory")
#define PAIRBAR(id)  asm volatile("bar.sync %0, 64;" :: "r"(id) : "memory")

// pair-split load of one X chunk: warp loads rows 16*wh..+15, cols 16*ns..+15.
// Pair {w, w+8} (same wh, ns=0/1) jointly covers rows 16*wh x 32 cols.
static __device__ __forceinline__ void load_chunkX_p(
    const float* __restrict__ gsrc, float* slot, int wh, int ns, int lane) {
    #pragma unroll
    for (int p = 0; p < 2; p++) {
        int f = lane + 32 * p;          // 0..63 float4s
        int mr = f >> 2, u = f & 3;
        int m = 16 * wh + mr;
        int c4 = 4 * ns + u;
        uint32_t dst = smem_u32(slot + m * 32 + 4 * (c4 ^ (m & 7)));
        CPA16(dst, gsrc + m * SDIM + 4 * c4);
    }
}

// per-warp load of one eps chunk e (16 rows x 16 cols) into its private buffer
// chunk e: rows 32*wq + 16*(e&1) .., cols 64*nq + 16*(e>>1) ..
static __device__ __forceinline__ void load_eps(
    const float* __restrict__ eT, int e, int wq, int nq, int lane, float* ebuf) {
    #pragma unroll
    for (int p = 0; p < 2; p++) {
        int f = lane + 32 * p;          // 0..63 float4s
        int rr = f >> 2, u = f & 3;
        uint32_t dst = smem_u32(ebuf + rr * 16 + 4 * (u ^ (rr & 3)));
        CPA16(dst, eT + (32 * wq + 16 * (e & 1) + rr) * SDIM
                     + 64 * nq + 16 * (e >> 1) + 4 * u);
    }
}

__global__ void __launch_bounds__(NTHREADS, 1) mvn_er_kernel(
    const float* __restrict__ x, const float* __restrict__ eps,
    const float* __restrict__ W1, const float* __restrict__ b1,
    const float* __restrict__ W2, const float* __restrict__ b2,
    float* __restrict__ out, int numTiles)
{
    extern __shared__ float sm[];
    uint32_t* smu = reinterpret_cast<uint32_t*>(sm);

    const int tid  = threadIdx.x;
    const int w    = tid >> 5;
    const int wh   = w & 7;       // GEMM1 row group (16 rows); pair id
    const int ns   = w >> 3;      // GEMM1 column half
    const int wq   = w & 3;       // GEMM2 row quad (32 rows)
    const int nq   = w >> 2;      // GEMM2 column quarter (64 cols)
    const int lane = tid & 31;
    const int g    = lane >> 2;
    const int t4   = lane & 3;
    const int pbar = 1 + wh;      // named barrier id for this pair (1..8)

    // ---- stage weights (tf32, XOR-swizzled) + biases ----
    #pragma unroll 4
    for (int j = 0; j < 32; j++) {
        int idx = tid + NTHREADS * j;
        int kk = idx >> 6, n = idx & 63;
        smu[W1F + kk * 64 + (n ^ (8 * (kk & 3)))] = to_tf32(W1[idx]);
    }
    #pragma unroll 4
    for (int j = 0; j < 32; j++) {
        int idx = tid + NTHREADS * j;
        int kk = idx >> 8, n = idx & 255;
        smu[W2F + kk * 256 + (n ^ (8 * (kk & 3)))] = to_tf32(W2[idx]);
    }
    if (tid < 64) sm[B1S + tid] = b1[tid];
    if (tid >= 64 && tid < 320) sm[B2S + tid - 64] = b2[tid - 64];
    __syncthreads();

    const int G = gridDim.x;
    const long long TS = (long long)TMR * SDIM;
    int t = blockIdx.x;

    float* slot0 = sm + XSF;
    float* slot1 = sm + XSF + 4096;
    float* ebuf0 = sm + EPF + w * 512;
    float* ebuf1 = ebuf0 + 256;
    const uint32_t* Hs = smu + HSF;

    // pair-split prefetch of first tile's chunks 0,1
    load_chunkX_p(x + t * TS + 0 * 32, slot0, wh, ns, lane); CPCOMMIT();
    load_chunkX_p(x + t * TS + 1 * 32, slot1, wh, ns, lane); CPCOMMIT();

    const int arowX = (16 * wh + g) * 32 + t4;   // X A-fragment base

    for (; t < numTiles; t += G) {
        const long long base = t * TS;
        const float* xT = x + base;
        const float* eT = eps + base;
        float* oT = out + base;

        // ======== GEMM1: pair-synchronized, no block barriers ========
        float acc1[4][4];
        #pragma unroll
        for (int nt = 0; nt < 4; nt++)
            acc1[nt][0] = acc1[nt][1] = acc1[nt][2] = acc1[nt][3] = 0.0f;

        #pragma unroll
        for (int c = 0; c < 8; c++) {
            CPWAIT1();          // own cp.asyncs for chunk c done
            PAIRBAR(pbar);      // partner's too; cross-warp visibility
            const float* xs = (c & 1) ? slot1 : slot0;

            #pragma unroll
            for (int ks = 0; ks < 4; ks++) {
                int a0i = arowX + 4 * ((2 * ks) ^ g);
                uint32_t A0 = to_tf32(xs[a0i]);
                uint32_t A1 = to_tf32(xs[a0i + 256]);
                uint32_t A2 = to_tf32(xs[a0i ^ 4]);
                uint32_t A3 = to_tf32(xs[(a0i ^ 4) + 256]);
                const uint32_t* bp = smu + W1F + (32 * c + 8 * ks + t4) * 64 + 32 * ns + g;
                #pragma unroll
                for (int nt = 0; nt < 4; nt++) {
                    int o = 8 * (nt ^ t4);
                    mma8(acc1[nt], A0, A1, A2, A3, bp[o], bp[o + 256]);
                }
            }
            PAIRBAR(pbar);      // both warps done reading this slot's rows

            float* slot = (c & 1) ? slot1 : slot0;
            if (c < 6) {
                load_chunkX_p(xT + (c + 2) * 32, slot, wh, ns, lane);
            } else {
                int tn = t + G;
                if (tn < numTiles)
                    load_chunkX_p(x + tn * TS + (c - 6) * 32, slot, wh, ns, lane);
                // bundle eps chunks 0/1 for THIS tile's epilogue
                load_eps(eT, c - 6, wq, nq, lane, (c == 6) ? ebuf0 : ebuf1);
            }
            CPCOMMIT();
        }

        // ---- bias + relu -> H (tf32, swizzled) ----
        {
            const int m0 = (16 * wh + g) * 64;
            #pragma unroll
            for (int nt = 0; nt < 4; nt++) {
                int col = 32 * ns + 8 * nt + 2 * t4;
                float2 bb = *reinterpret_cast<const float2*>(&sm[B1S + col]);
                uint2 p0, p1;
                p0.x = to_tf32(fmaxf(acc1[nt][0] + bb.x, 0.0f));
                p0.y = to_tf32(fmaxf(acc1[nt][1] + bb.y, 0.0f));
                p1.x = to_tf32(fmaxf(acc1[nt][2] + bb.x, 0.0f));
                p1.y = to_tf32(fmaxf(acc1[nt][3] + bb.y, 0.0f));
                int hi = m0 + 4 * ((col >> 2) ^ g) + (col & 3);
                *reinterpret_cast<uint2*>(&smu[HSF + hi])       = p0;
                *reinterpret_cast<uint2*>(&smu[HSF + hi + 512]) = p1;
            }
        }
        __syncthreads();   // block barrier 1: H ready

        // ---- preload H A-fragments for BOTH m-frags (rows 32wq..+31) ----
        uint4 hA[16];
        #pragma unroll
        for (int mf = 0; mf < 2; mf++) {
            const int arowH = (32 * wq + 16 * mf + g) * 64 + t4;
            #pragma unroll
            for (int ks = 0; ks < 8; ks++) {
                int a0i = arowH + 4 * ((2 * ks) ^ g);
                hA[8 * mf + ks].x = Hs[a0i];
                hA[8 * mf + ks].y = Hs[a0i + 512];
                hA[8 * mf + ks].z = Hs[a0i ^ 4];
                hA[8 * mf + ks].w = Hs[(a0i ^ 4) + 512];
            }
        }
        __syncthreads();   // block barrier 2: H retired — epilogue + next-tile
                           // GEMM1 run with no block-wide barriers

        // ======== GEMM2 + epilogue: 4 j-chunks of 16 cols, rows 32wq..+31 ========
        #pragma unroll
        for (int j = 0; j < 4; j++) {
            const int colb = 64 * nq + 16 * j + 2 * t4;

            // x loads for half 0 (hidden under MMAs)
            float2 xv0[2][2];
            #pragma unroll
            for (int nt = 0; nt < 2; nt++)
                #pragma unroll
                for (int hi = 0; hi < 2; hi++)
                    xv0[nt][hi] = *reinterpret_cast<const float2*>(
                        &xT[(32 * wq + 8 * hi + g) * SDIM + colb + 8 * nt]);

            float acc2[2][2][4];
            #pragma unroll
            for (int mf = 0; mf < 2; mf++)
                #pragma unroll
                for (int nt = 0; nt < 2; nt++)
                    acc2[mf][nt][0] = acc2[mf][nt][1] =
                    acc2[mf][nt][2] = acc2[mf][nt][3] = 0.0f;

            const int nc0 = 64 * nq + 16 * j + g;
            const int i0 = nc0 ^ (8 * t4);
            const int i1 = (nc0 + 8) ^ (8 * t4);
            #pragma unroll
            for (int ks = 0; ks < 8; ks++) {
                const uint32_t* bp = smu + W2F + (8 * ks + t4) * 256;
                uint32_t b00 = bp[i0], b01 = bp[i1];
                uint32_t b10 = bp[1024 + i0], b11 = bp[1024 + i1];
                mma8(acc2[0][0], hA[ks].x, hA[ks].y, hA[ks].z, hA[ks].w, b00, b10);
                mma8(acc2[0][1], hA[ks].x, hA[ks].y, hA[ks].z, hA[ks].w, b01, b11);
                mma8(acc2[1][0], hA[8+ks].x, hA[8+ks].y, hA[8+ks].z, hA[8+ks].w, b00, b10);
                mma8(acc2[1][1], hA[8+ks].x, hA[8+ks].y, hA[8+ks].z, hA[8+ks].w, b01, b11);
            }

            float2 bb[2];
            bb[0] = *reinterpret_cast<const float2*>(&sm[B2S + colb]);
            bb[1] = *reinterpret_cast<const float2*>(&sm[B2S + colb + 8]);

            // ---- half 0 (rows 32wq..+15, eps chunk 2j in ebuf0) ----
            CPWAIT1();
            __syncwarp();
            #pragma unroll
            for (int nt = 0; nt < 2; nt++) {
                #pragma unroll
                for (int hi = 0; hi < 2; hi++) {
                    int rr = g + 8 * hi;
                    int u  = (2 * nt + (t4 >> 1)) ^ (rr & 3);
                    float2 ev = *reinterpret_cast<const float2*>(
                        &ebuf0[rr * 16 + 4 * u + 2 * (t4 & 1)]);
                    int row = 32 * wq + 8 * hi + g;
                    float s0 = ex2f((acc2[0][nt][2 * hi]     + bb[nt].x) * 0.72134752044f);
                    float s1 = ex2f((acc2[0][nt][2 * hi + 1] + bb[nt].y) * 0.72134752044f);
                    float2 o;
                    o.x = fmaf(s0, ev.x, xv0[nt][hi].x);
                    o.y = fmaf(s1, ev.y, xv0[nt][hi].y);
                    *reinterpret_cast<float2*>(&oT[row * SDIM + colb + 8 * nt]) = o;
                }
            }
            __syncwarp();
            if (2 * j + 2 < 8) load_eps(eT, 2 * j + 2, wq, nq, lane, ebuf0);
            CPCOMMIT();

            // x loads for half 1
            float2 xv1[2][2];
            #pragma unroll
            for (int nt = 0; nt < 2; nt++)
                #pragma unroll
                for (int hi = 0; hi < 2; hi++)
                    xv1[nt][hi] = *reinterpret_cast<const float2*>(
                        &xT[(32 * wq + 16 + 8 * hi + g) * SDIM + colb + 8 * nt]);

            // ---- half 1 (rows 32wq+16..+31, eps chunk 2j+1 in ebuf1) ----
            CPWAIT1();
            __syncwarp();
            #pragma unroll
            for (int nt = 0; nt < 2; nt++) {
                #pragma unroll
                for (int hi = 0; hi < 2; hi++) {
                    int rr = g + 8 * hi;
                    int u  = (2 * nt + (t4 >> 1)) ^ (rr & 3);
                    float2 ev = *reinterpret_cast<const float2*>(
                        &ebuf1[rr * 16 + 4 * u + 2 * (t4 & 1)]);
                    int row = 32 * wq + 16 + 8 * hi + g;
                    float s0 = ex2f((acc2[1][nt][2 * hi]     + bb[nt].x) * 0.72134752044f);
                    float s1 = ex2f((acc2[1][nt][2 * hi + 1] + bb[nt].y) * 0.72134752044f);
                    float2 o;
                    o.x = fmaf(s0, ev.x, xv1[nt][hi].x);
                    o.y = fmaf(s1, ev.y, xv1[nt][hi].y);
                    *reinterpret_cast<float2*>(&oT[row * SDIM + colb + 8 * nt]) = o;
                }
            }
            __syncwarp();
            if (2 * j + 3 < 8) load_eps(eT, 2 * j + 3, wq, nq, lane, ebuf1);
            CPCOMMIT();
        }
        // NO end-of-tile block barrier: H already retired at barrier 2;
        // X-slot ordering is enforced by the pair barriers in GEMM1.
    }
}

extern "C" void kernel_launch(void* const* d_in, const int* in_sizes, int n_in,
                              void* d_out, int out_size) {
    const float* x   = (const float*)d_in[0];
    const float* eps = (const float*)d_in[1];
    const float* W1  = (const float*)d_in[2];
    const float* b1  = (const float*)d_in[3];
    const float* W2  = (const float*)d_in[4];
    const float* b2  = (const float*)d_in[5];
    float* out = (float*)d_out;

    int B = in_sizes[0] / SDIM;
    int numTiles = B / TMR;   // 1024

    static int sms = 0;
    if (!sms) {
        cudaDeviceGetAttribute(&sms, cudaDevAttrMultiProcessorCount, 0);
        cudaFuncSetAttribute(mvn_er_kernel,
                             cudaFuncAttributeMaxDynamicSharedMemorySize, SMEM_BYTES);
    }
    int grid = sms < numTiles ? sms : numTiles;

    mvn_er_kernel<<<grid, NTHREADS, SMEM_BYTES>>>(x, eps, W1, b1, W2, b2, out, numTiles);
}